// round 15
// baseline (speedup 1.0000x reference)
#include <cuda_runtime.h>
#include <cuda_bf16.h>
#include <math.h>
#include <stdint.h>

#define BB  2
#define SS  2048
#define HH  1024
#define NHH 16
#define HD  64
#define MROWS (BB*SS)      // 4096
#define GK  1024

#define QTILE 128
#define KTILE 64

// ---------------- scratch (no allocations allowed) ----------------
__device__ float g_Q[(size_t)BB*SS*HH];
__device__ float g_K[(size_t)BB*SS*HH];
__device__ float g_V[(size_t)BB*SS*HH];
__device__ float g_CTX[(size_t)BB*SS*HH];
__device__ float g_Xc[(size_t)MROWS*HH];       // X pre-rounded to tf32
__device__ float g_Wc0[(size_t)GK*HH];
__device__ float g_Wc1[(size_t)GK*HH];
__device__ float g_Wc2[(size_t)GK*HH];
__device__ float g_Wc3[(size_t)GK*HH];

// =================================================================
// helpers
// =================================================================
__device__ __forceinline__ uint32_t f2tf32(float x) {
    uint32_t u;
    asm("cvt.rna.tf32.f32 %0, %1;" : "=r"(u) : "f"(x));
    return u;
}
__device__ __forceinline__ float cvtf(float x) {
    return __uint_as_float(f2tf32(x));
}
__device__ __forceinline__ void mma_tf32_16n8k8(float* c,
    uint32_t a0, uint32_t a1, uint32_t a2, uint32_t a3,
    uint32_t b0, uint32_t b1)
{
    asm volatile("mma.sync.aligned.m16n8k8.row.col.f32.tf32.tf32.f32 "
        "{%0,%1,%2,%3},{%4,%5,%6,%7},{%8,%9},{%0,%1,%2,%3};"
        : "+f"(c[0]), "+f"(c[1]), "+f"(c[2]), "+f"(c[3])
        : "r"(a0), "r"(a1), "r"(a2), "r"(a3), "r"(b0), "r"(b1));
}
__device__ __forceinline__ void ldsm4(uint32_t& r0, uint32_t& r1,
                                      uint32_t& r2, uint32_t& r3, uint32_t a) {
    asm volatile("ldmatrix.sync.aligned.m8n8.x4.shared.b16 {%0,%1,%2,%3}, [%4];"
        : "=r"(r0), "=r"(r1), "=r"(r2), "=r"(r3) : "r"(a));
}
__device__ __forceinline__ int permc(int h) {
    return (h & ~7) | ((h & 3) << 1) | ((h >> 2) & 1);
}

// =================================================================
// elementwise tf32-round pre-pass
// =================================================================
__global__ void cvt_tf32_kernel(const float* __restrict__ src,
                                float* __restrict__ dst, int n4)
{
    int i = blockIdx.x * blockDim.x + threadIdx.x;
    if (i < n4) {
        float4 v = reinterpret_cast<const float4*>(src)[i];
        v.x = cvtf(v.x); v.y = cvtf(v.y); v.z = cvtf(v.z); v.w = cvtf(v.w);
        reinterpret_cast<float4*>(dst)[i] = v;
    }
}

// =================================================================
// GEMM: C[4096,1024] = A @ W, inputs pre-rounded to tf32.
// mode: 0 = plain row-major out (raw fp32)
//       1 = Q: [B,NH,S,HD], hd permc'd, *0.125, tf32-rounded
//       2 = K: [B,NH,S,HD], hd permc'd, tf32-rounded
//       3 = V: [B,NH,S,HD], plain hd, tf32-rounded
// =================================================================
#define STAGES 3
#define SA_ST 36
#define SB_ST 136
#define SA_TILE (128 * SA_ST)
#define SB_TILE (32 * SB_ST)

__global__ __launch_bounds__(128) void gemm_tf32_cp(
    const float* __restrict__ A, const float* __restrict__ Wm,
    float* __restrict__ C, int mode)
{
    extern __shared__ float sm[];
    float* sB = sm + STAGES * SA_TILE;

    const int tid  = threadIdx.x;
    const int wid  = tid >> 5;
    const int lane = tid & 31;
    const int gi   = lane >> 2;
    const int ti   = lane & 3;
    const int wm   = wid >> 1;
    const int wn   = wid & 1;
    const int m0   = blockIdx.y * 128;
    const int n0   = blockIdx.x * 128;

    const float* Abase = A + (size_t)m0 * GK;
    const float* Bbase = Wm + n0;
    const uint32_t smbase = (uint32_t)__cvta_generic_to_shared(sm);

    const int acr = tid >> 3, acs = (tid & 7) << 2;
    const int bcr = tid >> 5, bcs = (tid & 31) << 2;

    #define ISSUE_TILE(kt, stg)                                              \
    {                                                                        \
        uint32_t sa_ = smbase + (uint32_t)(stg) * SA_TILE * 4;               \
        uint32_t sb_ = smbase + (uint32_t)(STAGES * SA_TILE +                \
                                           (stg) * SB_TILE) * 4;             \
        const float* ga_ = Abase + (kt) * 32;                                \
        const float* gb_ = Bbase + (size_t)(kt) * 32 * HH;                   \
        _Pragma("unroll")                                                    \
        for (int i_ = 0; i_ < 8; i_++) {                                     \
            int r_ = acr + i_ * 16;                                          \
            asm volatile("cp.async.cg.shared.global [%0],[%1],16;" ::        \
                "r"(sa_ + (uint32_t)(r_ * SA_ST + acs) * 4),                 \
                "l"(ga_ + (size_t)r_ * GK + acs));                           \
        }                                                                    \
        _Pragma("unroll")                                                    \
        for (int i_ = 0; i_ < 8; i_++) {                                     \
            int r_ = bcr + i_ * 4;                                           \
            asm volatile("cp.async.cg.shared.global [%0],[%1],16;" ::        \
                "r"(sb_ + (uint32_t)(r_ * SB_ST + bcs) * 4),                 \
                "l"(gb_ + (size_t)r_ * HH + bcs));                           \
        }                                                                    \
        asm volatile("cp.async.commit_group;");                              \
    }

    float acc[4][8][4];
    #pragma unroll
    for (int mi = 0; mi < 4; mi++)
        #pragma unroll
        for (int ni = 0; ni < 8; ni++)
            #pragma unroll
            for (int e = 0; e < 4; e++) acc[mi][ni][e] = 0.0f;

    ISSUE_TILE(0, 0);
    ISSUE_TILE(1, 1);

    const int      lrow   = wm * 64 + (lane & 15);
    const uint32_t lcol16 = (lane & 16) ? 16u : 0u;

    const int NKT = GK / 32;
    for (int kt = 0; kt < NKT; kt++) {
        asm volatile("cp.async.wait_group 1;");
        __syncthreads();

        const int stg = kt % STAGES;
        const uint32_t saU = smbase + (uint32_t)stg * SA_TILE * 4;
        const float* sBc = sB + stg * SB_TILE;

        #pragma unroll
        for (int ks = 0; ks < 4; ks++) {
            uint32_t af[4][4];
            #pragma unroll
            for (int mi = 0; mi < 4; mi++) {
                uint32_t addr = saU + (uint32_t)(((lrow + mi * 16) * SA_ST + ks * 8) * 4) + lcol16;
                ldsm4(af[mi][0], af[mi][1], af[mi][2], af[mi][3], addr);
            }
            #pragma unroll
            for (int ni = 0; ni < 8; ni++) {
                int nc = wn * 64 + ni * 8 + gi;
                uint32_t b0 = __float_as_uint(sBc[(ks * 8 + ti) * SB_ST + nc]);
                uint32_t b1 = __float_as_uint(sBc[(ks * 8 + ti + 4) * SB_ST + nc]);
                #pragma unroll
                for (int mi = 0; mi < 4; mi++)
                    mma_tf32_16n8k8(acc[mi][ni], af[mi][0], af[mi][1], af[mi][2], af[mi][3], b0, b1);
            }
        }
        if (kt + 2 < NKT) ISSUE_TILE(kt + 2, (kt + 2) % STAGES);
    }

    // ---- epilogue ----
    #pragma unroll
    for (int mi = 0; mi < 4; mi++) {
        #pragma unroll
        for (int ni = 0; ni < 8; ni++) {
            int r0 = m0 + wm * 64 + mi * 16 + gi;
            int c0 = n0 + wn * 64 + ni * 8 + 2 * ti;
            float v0 = acc[mi][ni][0], v1 = acc[mi][ni][1];
            float v2 = acc[mi][ni][2], v3 = acc[mi][ni][3];
            if (mode == 0) {
                *reinterpret_cast<float2*>(&C[(size_t)r0 * HH + c0]) = make_float2(v0, v1);
                *reinterpret_cast<float2*>(&C[(size_t)(r0 + 8) * HH + c0]) = make_float2(v2, v3);
            } else {
                int h  = c0 >> 6;
                int hd = c0 & (HD - 1);
                int b0_ = r0 >> 11, s0_ = r0 & (SS - 1);
                int r1 = r0 + 8;
                int b1_ = r1 >> 11, s1_ = r1 & (SS - 1);
                float* p0 = C + (((size_t)(b0_ * NHH + h) * SS + s0_) << 6);
                float* p1 = C + (((size_t)(b1_ * NHH + h) * SS + s1_) << 6);
                if (mode == 1) {
                    p0[permc(hd)]     = cvtf(v0 * 0.125f);
                    p0[permc(hd + 1)] = cvtf(v1 * 0.125f);
                    p1[permc(hd)]     = cvtf(v2 * 0.125f);
                    p1[permc(hd + 1)] = cvtf(v3 * 0.125f);
                } else if (mode == 2) {
                    p0[permc(hd)]     = cvtf(v0);
                    p0[permc(hd + 1)] = cvtf(v1);
                    p1[permc(hd)]     = cvtf(v2);
                    p1[permc(hd + 1)] = cvtf(v3);
                } else {
                    *reinterpret_cast<float2*>(p0 + hd) = make_float2(cvtf(v0), cvtf(v1));
                    *reinterpret_cast<float2*>(p1 + hd) = make_float2(cvtf(v2), cvtf(v3));
                }
            }
        }
    }
    #undef ISSUE_TILE
}

// =================================================================
// Flash attention v5 = R10 structure (validated 324us) with the
// load path reduced to plain float4 copies: Q/K pre-permuted,
// Q prescaled, all pre-tf32-rounded by the GEMM epilogue.
// Single-buffered K/V, same smem (69KB), same barriers, same regs.
// =================================================================
__global__ __launch_bounds__(128, 2) void attn_kernel(
    const float* __restrict__ Qg, const float* __restrict__ Kg,
    const float* __restrict__ Vg, const int* __restrict__ maskg,
    float* __restrict__ CTX)
{
    extern __shared__ float smbuf[];
    float* sQ = smbuf;                       // [128][68]
    float* sK = sQ + 128 * 68;               // [64][68]
    float* sV = sK + 64 * 68;                // [64][72]
    int*   sM = (int*)(sV + 64 * 72);        // [64]

    const int tid  = threadIdx.x;
    const int wid  = tid >> 5;
    const int lane = tid & 31;
    const int gi   = lane >> 2;
    const int ti   = lane & 3;
    const int q0   = blockIdx.x * QTILE;
    const int h    = blockIdx.y;
    const int b    = blockIdx.z;
    const size_t off = ((size_t)(b * NHH + h) * SS) << 6;
    const float* Qb = Qg + off + ((size_t)q0 << 6);
    const float* Kb = Kg + off;
    const float* Vb = Vg + off;
    const int*   Mb = maskg + (size_t)b * SS;

    // ---- load Q tile (plain copy; already permuted/scaled/rounded) ----
    #pragma unroll
    for (int i = 0; i < 16; i++) {
        int lin = tid + i * 128;
        int r = lin >> 4;
        int c4 = (lin & 15) << 2;
        *reinterpret_cast<float4*>(&sQ[r * 68 + c4]) =
            *reinterpret_cast<const float4*>(&Qb[((size_t)r << 6) + c4]);
    }

    float o0[8][4], o1[8][4];
    #pragma unroll
    for (int j = 0; j < 8; j++)
        #pragma unroll
        for (int e = 0; e < 4; e++) { o0[j][e] = 0.0f; o1[j][e] = 0.0f; }
    float m00 = -INFINITY, m01 = -INFINITY, m10 = -INFINITY, m11 = -INFINITY;
    float l00 = 0.0f, l01 = 0.0f, l10 = 0.0f, l11 = 0.0f;

    const int ar0 = wid * 32 + gi;

    for (int kt = 0; kt < SS / KTILE; kt++) {
        const int k0 = kt * KTILE;

        // ---- load K / V tiles (plain copies) + mask ints ----
        #pragma unroll
        for (int i = 0; i < 8; i++) {
            int lin = tid + i * 128;
            int r = lin >> 4;
            int c4 = (lin & 15) << 2;
            *reinterpret_cast<float4*>(&sK[r * 68 + c4]) =
                *reinterpret_cast<const float4*>(&Kb[((size_t)(k0 + r) << 6) + c4]);
            *reinterpret_cast<float4*>(&sV[r * 72 + c4]) =
                *reinterpret_cast<const float4*>(&Vb[((size_t)(k0 + r) << 6) + c4]);
        }
        if (tid < KTILE) sM[tid] = Mb[k0 + tid];
        __syncthreads();

        // ---- S = Q @ K^T, both strips, K fragments shared ----
        float s0[8][4], s1[8][4];
        #pragma unroll
        for (int j = 0; j < 8; j++)
            #pragma unroll
            for (int e = 0; e < 4; e++) { s0[j][e] = 0.0f; s1[j][e] = 0.0f; }

        #pragma unroll
        for (int ks = 0; ks < 8; ks++) {
            const float* qp = &sQ[ar0 * 68 + ks * 8 + 2 * ti];
            float2 qa0 = *reinterpret_cast<const float2*>(qp);
            float2 qa1 = *reinterpret_cast<const float2*>(qp + 8 * 68);
            float2 qa2 = *reinterpret_cast<const float2*>(qp + 16 * 68);
            float2 qa3 = *reinterpret_cast<const float2*>(qp + 24 * 68);
            uint32_t a00 = __float_as_uint(qa0.x), a02 = __float_as_uint(qa0.y);
            uint32_t a01 = __float_as_uint(qa1.x), a03 = __float_as_uint(qa1.y);
            uint32_t a10 = __float_as_uint(qa2.x), a12 = __float_as_uint(qa2.y);
            uint32_t a11 = __float_as_uint(qa3.x), a13 = __float_as_uint(qa3.y);
            #pragma unroll
            for (int j = 0; j < 8; j++) {
                float2 kb = *reinterpret_cast<const float2*>(&sK[(j * 8 + gi) * 68 + ks * 8 + 2 * ti]);
                uint32_t b0 = __float_as_uint(kb.x), b1 = __float_as_uint(kb.y);
                mma_tf32_16n8k8(s0[j], a00, a01, a02, a03, b0, b1);
                mma_tf32_16n8k8(s1[j], a10, a11, a12, a13, b0, b1);
            }
        }

        // ---- bias from mask ints ----
        float bias0[8], bias1[8];
        #pragma unroll
        for (int j = 0; j < 8; j++) {
            bias0[j] = (sM[j * 8 + 2 * ti] == 0) ? -1e30f : 0.0f;
            bias1[j] = (sM[j * 8 + 2 * ti + 1] == 0) ? -1e30f : 0.0f;
        }

        // ---- online softmax, strip 0 ----
        {
            float mloc0 = -INFINITY, mloc1 = -INFINITY;
            #pragma unroll
            for (int j = 0; j < 8; j++) {
                s0[j][0] = fminf(fmaxf(s0[j][0], -10000.0f), 10000.0f) + bias0[j];
                s0[j][1] = fminf(fmaxf(s0[j][1], -10000.0f), 10000.0f) + bias1[j];
                s0[j][2] = fminf(fmaxf(s0[j][2], -10000.0f), 10000.0f) + bias0[j];
                s0[j][3] = fminf(fmaxf(s0[j][3], -10000.0f), 10000.0f) + bias1[j];
                mloc0 = fmaxf(mloc0, fmaxf(s0[j][0], s0[j][1]));
                mloc1 = fmaxf(mloc1, fmaxf(s0[j][2], s0[j][3]));
            }
            mloc0 = fmaxf(mloc0, __shfl_xor_sync(0xffffffffu, mloc0, 1));
            mloc0 = fmaxf(mloc0, __shfl_xor_sync(0xffffffffu, mloc0, 2));
            mloc1 = fmaxf(mloc1, __shfl_xor_sync(0xffffffffu, mloc1, 1));
            mloc1 = fmaxf(mloc1, __shfl_xor_sync(0xffffffffu, mloc1, 2));
            float mn0 = fmaxf(m00, mloc0);
            float mn1 = fmaxf(m01, mloc1);
            float corr0 = __expf(m00 - mn0);
            float corr1 = __expf(m01 - mn1);
            m00 = mn0; m01 = mn1;
            float sum0 = 0.0f, sum1 = 0.0f;
            #pragma unroll
            for (int j = 0; j < 8; j++) {
                s0[j][0] = __expf(s0[j][0] - mn0);
                s0[j][1] = __expf(s0[j][1] - mn0);
                s0[j][2] = __expf(s0[j][2] - mn1);
                s0[j][3] = __expf(s0[j][3] - mn1);
                sum0 += s0[j][0] + s0[j][1];
                sum1 += s0[j][2] + s0[j][3];
            }
            sum0 += __shfl_xor_sync(0xffffffffu, sum0, 1);
            sum0 += __shfl_xor_sync(0xffffffffu, sum0, 2);
            sum1 += __shfl_xor_sync(0xffffffffu, sum1, 1);
            sum1 += __shfl_xor_sync(0xffffffffu, sum1, 2);
            l00 = l00 * corr0 + sum0;
            l01 = l01 * corr1 + sum1;
            #pragma unroll
            for (int j = 0; j < 8; j++) {
                o0[j][0] *= corr0; o0[j][1] *= corr0;
                o0[j][2] *= corr1; o0[j][3] *= corr1;
            }
        }
        // ---- online softmax, strip 1 ----
        {
            float mloc0 = -INFINITY, mloc1 = -INFINITY;
            #pragma unroll
            for (int j = 0; j < 8; j++) {
                s1[j][0] = fminf(fmaxf(s1[j][0], -10000.0f), 10000.0f) + bias0[j];
                s1[j][1] = fminf(fmaxf(s1[j][1], -10000.0f), 10000.0f) + bias1[j];
                s1[j][2] = fminf(fmaxf(s1[j][2], -10000.0f), 10000.0f) + bias0[j];
                s1[j][3] = fminf(fmaxf(s1[j][3], -10000.0f), 10000.0f) + bias1[j];
                mloc0 = fmaxf(mloc0, fmaxf(s1[j][0], s1[j][1]));
                mloc1 = fmaxf(mloc1, fmaxf(s1[j][2], s1[j][3]));
            }
            mloc0 = fmaxf(mloc0, __shfl_xor_sync(0xffffffffu, mloc0, 1));
            mloc0 = fmaxf(mloc0, __shfl_xor_sync(0xffffffffu, mloc0, 2));
            mloc1 = fmaxf(mloc1, __shfl_xor_sync(0xffffffffu, mloc1, 1));
            mloc1 = fmaxf(mloc1, __shfl_xor_sync(0xffffffffu, mloc1, 2));
            float mn0 = fmaxf(m10, mloc0);
            float mn1 = fmaxf(m11, mloc1);
            float corr0 = __expf(m10 - mn0);
            float corr1 = __expf(m11 - mn1);
            m10 = mn0; m11 = mn1;
            float sum0 = 0.0f, sum1 = 0.0f;
            #pragma unroll
            for (int j = 0; j < 8; j++) {
                s1[j][0] = __expf(s1[j][0] - mn0);
                s1[j][1] = __expf(s1[j][1] - mn0);
                s1[j][2] = __expf(s1[j][2] - mn1);
                s1[j][3] = __expf(s1[j][3] - mn1);
                sum0 += s1[j][0] + s1[j][1];
                sum1 += s1[j][2] + s1[j][3];
            }
            sum0 += __shfl_xor_sync(0xffffffffu, sum0, 1);
            sum0 += __shfl_xor_sync(0xffffffffu, sum0, 2);
            sum1 += __shfl_xor_sync(0xffffffffu, sum1, 1);
            sum1 += __shfl_xor_sync(0xffffffffu, sum1, 2);
            l10 = l10 * corr0 + sum0;
            l11 = l11 * corr1 + sum1;
            #pragma unroll
            for (int j = 0; j < 8; j++) {
                o1[j][0] *= corr0; o1[j][1] *= corr0;
                o1[j][2] *= corr1; o1[j][3] *= corr1;
            }
        }

        // ---- O += P @ V, V fragments shared across strips ----
        {
            const int qb   = lane & ~3;
            const int src0 = qb + (ti >> 1);
            const int src1 = src0 + 2;
            const bool odd = (ti & 1);
            #pragma unroll
            for (int kb = 0; kb < 8; kb++) {
                float v00 = __shfl_sync(0xffffffffu, s0[kb][0], src0);
                float v01 = __shfl_sync(0xffffffffu, s0[kb][1], src0);
                float v20 = __shfl_sync(0xffffffffu, s0[kb][0], src1);
                float v21 = __shfl_sync(0xffffffffu, s0[kb][1], src1);
                float v10 = __shfl_sync(0xffffffffu, s0[kb][2], src0);
                float v11 = __shfl_sync(0xffffffffu, s0[kb][3], src0);
                float v30 = __shfl_sync(0xffffffffu, s0[kb][2], src1);
                float v31 = __shfl_sync(0xffffffffu, s0[kb][3], src1);
                uint32_t a0 = f2tf32(odd ? v01 : v00);
                uint32_t a1 = f2tf32(odd ? v11 : v10);
                uint32_t a2 = f2tf32(odd ? v21 : v20);
                uint32_t a3 = f2tf32(odd ? v31 : v30);
                float w00 = __shfl_sync(0xffffffffu, s1[kb][0], src0);
                float w01 = __shfl_sync(0xffffffffu, s1[kb][1], src0);
                float w20 = __shfl_sync(0xffffffffu, s1[kb][0], src1);
                float w21 = __shfl_sync(0xffffffffu, s1[kb][1], src1);
                float w10 = __shfl_sync(0xffffffffu, s1[kb][2], src0);
                float w11 = __shfl_sync(0xffffffffu, s1[kb][3], src0);
                float w30 = __shfl_sync(0xffffffffu, s1[kb][2], src1);
                float w31 = __shfl_sync(0xffffffffu, s1[kb][3], src1);
                uint32_t c0 = f2tf32(odd ? w01 : w00);
                uint32_t c1 = f2tf32(odd ? w11 : w10);
                uint32_t c2 = f2tf32(odd ? w21 : w20);
                uint32_t c3 = f2tf32(odd ? w31 : w30);
                #pragma unroll
                for (int j = 0; j < 8; j++) {
                    uint32_t b0 = __float_as_uint(sV[(kb * 8 + ti) * 72 + j * 8 + gi]);
                    uint32_t b1 = __float_as_uint(sV[(kb * 8 + ti + 4) * 72 + j * 8 + gi]);
                    mma_tf32_16n8k8(o0[j], a0, a1, a2, a3, b0, b1);
                    mma_tf32_16n8k8(o1[j], c0, c1, c2, c3, b0, b1);
                }
            }
        }
        __syncthreads();
    }

    // ---- normalize, round to tf32, write context [B, S, H] ----
    float i00 = 1.0f / l00, i01 = 1.0f / l01;
    float i10 = 1.0f / l10, i11 = 1.0f / l11;
    int row0 = q0 + wid * 32 + gi;
    #pragma unroll
    for (int j = 0; j < 8; j++) {
        int c = h * HD + j * 8 + 2 * ti;
        *reinterpret_cast<float2*>(&CTX[(size_t)(b * SS + row0) * HH + c]) =
            make_float2(cvtf(o0[j][0] * i00), cvtf(o0[j][1] * i00));
        *reinterpret_cast<float2*>(&CTX[(size_t)(b * SS + row0 + 8) * HH + c]) =
            make_float2(cvtf(o0[j][2] * i01), cvtf(o0[j][3] * i01));
        *reinterpret_cast<float2*>(&CTX[(size_t)(b * SS + row0 + 16) * HH + c]) =
            make_float2(cvtf(o1[j][0] * i10), cvtf(o1[j][1] * i10));
        *reinterpret_cast<float2*>(&CTX[(size_t)(b * SS + row0 + 24) * HH + c]) =
            make_float2(cvtf(o1[j][2] * i11), cvtf(o1[j][3] * i11));
    }
}

// =================================================================
extern "C" void kernel_launch(void* const* d_in, const int* in_sizes, int n_in,
                              void* d_out, int out_size)
{
    const float* X    = (const float*)d_in[0];
    const int*   mask = (const int*)d_in[1];
    const float* WQ   = (const float*)d_in[2];
    const float* WK   = (const float*)d_in[3];
    const float* WV   = (const float*)d_in[4];
    const float* WO   = (const float*)d_in[5];
    float* out = (float*)d_out;

    float *qb, *kb, *vb, *cb, *xc, *w0, *w1, *w2, *w3;
    cudaGetSymbolAddress((void**)&qb, g_Q);
    cudaGetSymbolAddress((void**)&kb, g_K);
    cudaGetSymbolAddress((void**)&vb, g_V);
    cudaGetSymbolAddress((void**)&cb, g_CTX);
    cudaGetSymbolAddress((void**)&xc, g_Xc);
    cudaGetSymbolAddress((void**)&w0, g_Wc0);
    cudaGetSymbolAddress((void**)&w1, g_Wc1);
    cudaGetSymbolAddress((void**)&w2, g_Wc2);
    cudaGetSymbolAddress((void**)&w3, g_Wc3);

    const int nx4 = MROWS * HH / 4;
    const int nw4 = GK * HH / 4;
    cvt_tf32_kernel<<<(nx4 + 255) / 256, 256>>>(X, xc, nx4);
    cvt_tf32_kernel<<<(nw4 + 255) / 256, 256>>>(WQ, w0, nw4);
    cvt_tf32_kernel<<<(nw4 + 255) / 256, 256>>>(WK, w1, nw4);
    cvt_tf32_kernel<<<(nw4 + 255) / 256, 256>>>(WV, w2, nw4);
    cvt_tf32_kernel<<<(nw4 + 255) / 256, 256>>>(WO, w3, nw4);

    size_t gsmem = (size_t)STAGES * (SA_TILE + SB_TILE) * sizeof(float);
    cudaFuncSetAttribute(gemm_tf32_cp, cudaFuncAttributeMaxDynamicSharedMemorySize, (int)gsmem);

    dim3 gg(HH / 128, MROWS / 128);   // (8, 32)
    gemm_tf32_cp<<<gg, 128, gsmem>>>(xc, w0, qb, 1);
    gemm_tf32_cp<<<gg, 128, gsmem>>>(xc, w1, kb, 2);
    gemm_tf32_cp<<<gg, 128, gsmem>>>(xc, w2, vb, 3);

    size_t smem = (size_t)(128 * 68 + 64 * 68 + 64 * 72) * sizeof(float)
                + 64 * sizeof(int);
    cudaFuncSetAttribute(attn_kernel, cudaFuncAttributeMaxDynamicSharedMemorySize, (int)smem);
    attn_kernel<<<dim3(SS / QTILE, NHH, BB), 128, smem>>>(qb, kb, vb, mask, cb);

    gemm_tf32_cp<<<gg, 128, gsmem>>>(cb, w3, out, 0);
}

// round 16
// speedup vs baseline: 1.6099x; 1.6099x over previous
#include <cuda_runtime.h>
#include <cuda_bf16.h>
#include <math.h>
#include <stdint.h>

#define BB  2
#define SS  2048
#define HH  1024
#define NHH 16
#define HD  64
#define MROWS (BB*SS)      // 4096
#define GK  1024

#define QTILE 128
#define KTILE 64

// ---------------- scratch (no allocations allowed) ----------------
__device__ float g_Q[(size_t)BB*SS*HH];
__device__ float g_K[(size_t)BB*SS*HH];
__device__ float g_V[(size_t)BB*SS*HH];
__device__ float g_CTX[(size_t)BB*SS*HH];
__device__ float g_Xc[(size_t)MROWS*HH];       // X pre-rounded to tf32
__device__ float g_Wc0[(size_t)GK*HH];
__device__ float g_Wc1[(size_t)GK*HH];
__device__ float g_Wc2[(size_t)GK*HH];
__device__ float g_Wc3[(size_t)GK*HH];

// =================================================================
// helpers
// =================================================================
__device__ __forceinline__ uint32_t f2tf32(float x) {
    uint32_t u;
    asm("cvt.rna.tf32.f32 %0, %1;" : "=r"(u) : "f"(x));
    return u;
}
__device__ __forceinline__ float cvtf(float x) {
    return __uint_as_float(f2tf32(x));
}
__device__ __forceinline__ void mma_tf32_16n8k8(float* c,
    uint32_t a0, uint32_t a1, uint32_t a2, uint32_t a3,
    uint32_t b0, uint32_t b1)
{
    asm volatile("mma.sync.aligned.m16n8k8.row.col.f32.tf32.tf32.f32 "
        "{%0,%1,%2,%3},{%4,%5,%6,%7},{%8,%9},{%0,%1,%2,%3};"
        : "+f"(c[0]), "+f"(c[1]), "+f"(c[2]), "+f"(c[3])
        : "r"(a0), "r"(a1), "r"(a2), "r"(a3), "r"(b0), "r"(b1));
}
__device__ __forceinline__ void ldsm4(uint32_t& r0, uint32_t& r1,
                                      uint32_t& r2, uint32_t& r3, uint32_t a) {
    asm volatile("ldmatrix.sync.aligned.m8n8.x4.shared.b16 {%0,%1,%2,%3}, [%4];"
        : "=r"(r0), "=r"(r1), "=r"(r2), "=r"(r3) : "r"(a));
}
__device__ __forceinline__ int permc(int h) {
    return (h & ~7) | ((h & 3) << 1) | ((h >> 2) & 1);
}

// =================================================================
// elementwise tf32-round pre-passes
// =================================================================
__global__ void cvt_tf32_kernel(const float* __restrict__ src,
                                float* __restrict__ dst, int n4)
{
    int i = blockIdx.x * blockDim.x + threadIdx.x;
    if (i < n4) {
        float4 v = reinterpret_cast<const float4*>(src)[i];
        v.x = cvtf(v.x); v.y = cvtf(v.y); v.z = cvtf(v.z); v.w = cvtf(v.w);
        reinterpret_cast<float4*>(dst)[i] = v;
    }
}
// 4 same-size tensors in one launch (blockIdx.y selects)
__global__ void cvt4_tf32_kernel(
    const float* __restrict__ s0, const float* __restrict__ s1,
    const float* __restrict__ s2, const float* __restrict__ s3,
    float* __restrict__ d0, float* __restrict__ d1,
    float* __restrict__ d2, float* __restrict__ d3, int n4)
{
    const float* s = (blockIdx.y == 0) ? s0 : (blockIdx.y == 1) ? s1
                   : (blockIdx.y == 2) ? s2 : s3;
    float* d = (blockIdx.y == 0) ? d0 : (blockIdx.y == 1) ? d1
             : (blockIdx.y == 2) ? d2 : d3;
    int i = blockIdx.x * blockDim.x + threadIdx.x;
    if (i < n4) {
        float4 v = reinterpret_cast<const float4*>(s)[i];
        v.x = cvtf(v.x); v.y = cvtf(v.y); v.z = cvtf(v.z); v.w = cvtf(v.w);
        reinterpret_cast<float4*>(d)[i] = v;
    }
}

// =================================================================
// GEMM (R10 body, validated ~51us/GEMM): C = A @ W, inputs
// pre-rounded tf32. gridDim.z selects (W, C) pair so Q/K/V run as
// ONE launch. permuted=1: write [B,NH,S,HD] (plain float2 stores).
// =================================================================
#define STAGES 3
#define SA_ST 36
#define SB_ST 136
#define SA_TILE (128 * SA_ST)
#define SB_TILE (32 * SB_ST)

__global__ __launch_bounds__(128) void gemm_tf32_cp(
    const float* __restrict__ A,
    const float* __restrict__ W0, const float* __restrict__ W1,
    const float* __restrict__ W2,
    float* __restrict__ C0, float* __restrict__ C1, float* __restrict__ C2,
    int permuted)
{
    const float* Wm = (blockIdx.z == 0) ? W0 : (blockIdx.z == 1) ? W1 : W2;
    float*       C  = (blockIdx.z == 0) ? C0 : (blockIdx.z == 1) ? C1 : C2;

    extern __shared__ float sm[];
    float* sB = sm + STAGES * SA_TILE;

    const int tid  = threadIdx.x;
    const int wid  = tid >> 5;
    const int lane = tid & 31;
    const int gi   = lane >> 2;
    const int ti   = lane & 3;
    const int wm   = wid >> 1;
    const int wn   = wid & 1;
    const int m0   = blockIdx.y * 128;
    const int n0   = blockIdx.x * 128;

    const float* Abase = A + (size_t)m0 * GK;
    const float* Bbase = Wm + n0;
    const uint32_t smbase = (uint32_t)__cvta_generic_to_shared(sm);

    const int acr = tid >> 3, acs = (tid & 7) << 2;
    const int bcr = tid >> 5, bcs = (tid & 31) << 2;

    #define ISSUE_TILE(kt, stg)                                              \
    {                                                                        \
        uint32_t sa_ = smbase + (uint32_t)(stg) * SA_TILE * 4;               \
        uint32_t sb_ = smbase + (uint32_t)(STAGES * SA_TILE +                \
                                           (stg) * SB_TILE) * 4;             \
        const float* ga_ = Abase + (kt) * 32;                                \
        const float* gb_ = Bbase + (size_t)(kt) * 32 * HH;                   \
        _Pragma("unroll")                                                    \
        for (int i_ = 0; i_ < 8; i_++) {                                     \
            int r_ = acr + i_ * 16;                                          \
            asm volatile("cp.async.cg.shared.global [%0],[%1],16;" ::        \
                "r"(sa_ + (uint32_t)(r_ * SA_ST + acs) * 4),                 \
                "l"(ga_ + (size_t)r_ * GK + acs));                           \
        }                                                                    \
        _Pragma("unroll")                                                    \
        for (int i_ = 0; i_ < 8; i_++) {                                     \
            int r_ = bcr + i_ * 4;                                           \
            asm volatile("cp.async.cg.shared.global [%0],[%1],16;" ::        \
                "r"(sb_ + (uint32_t)(r_ * SB_ST + bcs) * 4),                 \
                "l"(gb_ + (size_t)r_ * HH + bcs));                           \
        }                                                                    \
        asm volatile("cp.async.commit_group;");                              \
    }

    float acc[4][8][4];
    #pragma unroll
    for (int mi = 0; mi < 4; mi++)
        #pragma unroll
        for (int ni = 0; ni < 8; ni++)
            #pragma unroll
            for (int e = 0; e < 4; e++) acc[mi][ni][e] = 0.0f;

    ISSUE_TILE(0, 0);
    ISSUE_TILE(1, 1);

    const int      lrow   = wm * 64 + (lane & 15);
    const uint32_t lcol16 = (lane & 16) ? 16u : 0u;

    const int NKT = GK / 32;
    for (int kt = 0; kt < NKT; kt++) {
        asm volatile("cp.async.wait_group 1;");
        __syncthreads();

        const int stg = kt % STAGES;
        const uint32_t saU = smbase + (uint32_t)stg * SA_TILE * 4;
        const float* sBc = sB + stg * SB_TILE;

        #pragma unroll
        for (int ks = 0; ks < 4; ks++) {
            uint32_t af[4][4];
            #pragma unroll
            for (int mi = 0; mi < 4; mi++) {
                uint32_t addr = saU + (uint32_t)(((lrow + mi * 16) * SA_ST + ks * 8) * 4) + lcol16;
                ldsm4(af[mi][0], af[mi][1], af[mi][2], af[mi][3], addr);
            }
            #pragma unroll
            for (int ni = 0; ni < 8; ni++) {
                int nc = wn * 64 + ni * 8 + gi;
                uint32_t b0 = __float_as_uint(sBc[(ks * 8 + ti) * SB_ST + nc]);
                uint32_t b1 = __float_as_uint(sBc[(ks * 8 + ti + 4) * SB_ST + nc]);
                #pragma unroll
                for (int mi = 0; mi < 4; mi++)
                    mma_tf32_16n8k8(acc[mi][ni], af[mi][0], af[mi][1], af[mi][2], af[mi][3], b0, b1);
            }
        }
        if (kt + 2 < NKT) ISSUE_TILE(kt + 2, (kt + 2) % STAGES);
    }

    // ---- epilogue (R10: plain float2 stores, raw fp32) ----
    #pragma unroll
    for (int mi = 0; mi < 4; mi++) {
        #pragma unroll
        for (int ni = 0; ni < 8; ni++) {
            int r0 = m0 + wm * 64 + mi * 16 + gi;
            int c0 = n0 + wn * 64 + ni * 8 + 2 * ti;
            float v0 = acc[mi][ni][0], v1 = acc[mi][ni][1];
            float v2 = acc[mi][ni][2], v3 = acc[mi][ni][3];
            if (permuted) {
                int h  = c0 >> 6;
                int hd = c0 & (HD - 1);
                int b0_ = r0 >> 11, s0_ = r0 & (SS - 1);
                int r1 = r0 + 8;
                int b1_ = r1 >> 11, s1_ = r1 & (SS - 1);
                float* p0 = C + (((size_t)(b0_ * NHH + h) * SS + s0_) << 6) + hd;
                float* p1 = C + (((size_t)(b1_ * NHH + h) * SS + s1_) << 6) + hd;
                *reinterpret_cast<float2*>(p0) = make_float2(v0, v1);
                *reinterpret_cast<float2*>(p1) = make_float2(v2, v3);
            } else {
                *reinterpret_cast<float2*>(&C[(size_t)r0 * HH + c0]) = make_float2(v0, v1);
                *reinterpret_cast<float2*>(&C[(size_t)(r0 + 8) * HH + c0]) = make_float2(v2, v3);
            }
        }
    }
    #undef ISSUE_TILE
}

// =================================================================
// Flash attention (R10 body, validated 324us): 4 warps/CTA,
// 32 query rows per warp, cvtf+permc at smem store, scale folded
// into Q, CTX written tf32-rounded.
// =================================================================
__global__ __launch_bounds__(128, 2) void attn_kernel(
    const float* __restrict__ Q, const float* __restrict__ Kg,
    const float* __restrict__ Vg, const int* __restrict__ maskg,
    float* __restrict__ CTX)
{
    extern __shared__ float smbuf[];
    float* sQ = smbuf;                       // [128][68], permuted, tf32*0.125
    float* sK = sQ + 128 * 68;               // [64][68], permuted, tf32
    float* sV = sK + 64 * 68;                // [64 keys][72 hd], tf32
    float* sBias = sV + 64 * 72;             // [64]

    const int tid  = threadIdx.x;
    const int wid  = tid >> 5;
    const int lane = tid & 31;
    const int gi   = lane >> 2;
    const int ti   = lane & 3;
    const int q0   = blockIdx.x * QTILE;
    const int h    = blockIdx.y;
    const int b    = blockIdx.z;
    const size_t off = ((size_t)(b * NHH + h) * SS) << 6;

    #pragma unroll
    for (int i = 0; i < 16; i++) {
        int lin = tid + i * 128;
        int r = lin >> 4;
        int c4 = (lin & 15) << 2;
        float4 v = *reinterpret_cast<const float4*>(&Q[off + ((size_t)(q0 + r) << 6) + c4]);
        sQ[r * 68 + permc(c4 + 0)] = cvtf(v.x * 0.125f);
        sQ[r * 68 + permc(c4 + 1)] = cvtf(v.y * 0.125f);
        sQ[r * 68 + permc(c4 + 2)] = cvtf(v.z * 0.125f);
        sQ[r * 68 + permc(c4 + 3)] = cvtf(v.w * 0.125f);
    }

    float o0[8][4], o1[8][4];
    #pragma unroll
    for (int j = 0; j < 8; j++)
        #pragma unroll
        for (int e = 0; e < 4; e++) { o0[j][e] = 0.0f; o1[j][e] = 0.0f; }
    float m00 = -INFINITY, m01 = -INFINITY, m10 = -INFINITY, m11 = -INFINITY;
    float l00 = 0.0f, l01 = 0.0f, l10 = 0.0f, l11 = 0.0f;

    const int ar0 = wid * 32 + gi;

    for (int kt = 0; kt < SS / KTILE; kt++) {
        const int k0 = kt * KTILE;

        #pragma unroll
        for (int i = 0; i < 8; i++) {
            int lin = tid + i * 128;
            int r = lin >> 4;
            int c4 = (lin & 15) << 2;
            float4 vk = *reinterpret_cast<const float4*>(&Kg[off + ((size_t)(k0 + r) << 6) + c4]);
            sK[r * 68 + permc(c4 + 0)] = cvtf(vk.x);
            sK[r * 68 + permc(c4 + 1)] = cvtf(vk.y);
            sK[r * 68 + permc(c4 + 2)] = cvtf(vk.z);
            sK[r * 68 + permc(c4 + 3)] = cvtf(vk.w);
            float4 vv = *reinterpret_cast<const float4*>(&Vg[off + ((size_t)(k0 + r) << 6) + c4]);
            float4 t;
            t.x = cvtf(vv.x); t.y = cvtf(vv.y); t.z = cvtf(vv.z); t.w = cvtf(vv.w);
            *reinterpret_cast<float4*>(&sV[r * 72 + c4]) = t;
        }
        if (tid < KTILE)
            sBias[tid] = (maskg[b * SS + k0 + tid] == 0) ? -1e30f : 0.0f;
        __syncthreads();

        float s0[8][4], s1[8][4];
        #pragma unroll
        for (int j = 0; j < 8; j++)
            #pragma unroll
            for (int e = 0; e < 4; e++) { s0[j][e] = 0.0f; s1[j][e] = 0.0f; }

        #pragma unroll
        for (int ks = 0; ks < 8; ks++) {
            const float* qp = &sQ[ar0 * 68 + ks * 8 + 2 * ti];
            float2 qa0 = *reinterpret_cast<const float2*>(qp);
            float2 qa1 = *reinterpret_cast<const float2*>(qp + 8 * 68);
            float2 qa2 = *reinterpret_cast<const float2*>(qp + 16 * 68);
            float2 qa3 = *reinterpret_cast<const float2*>(qp + 24 * 68);
            uint32_t a00 = __float_as_uint(qa0.x), a02 = __float_as_uint(qa0.y);
            uint32_t a01 = __float_as_uint(qa1.x), a03 = __float_as_uint(qa1.y);
            uint32_t a10 = __float_as_uint(qa2.x), a12 = __float_as_uint(qa2.y);
            uint32_t a11 = __float_as_uint(qa3.x), a13 = __float_as_uint(qa3.y);
            #pragma unroll
            for (int j = 0; j < 8; j++) {
                float2 kb = *reinterpret_cast<const float2*>(&sK[(j * 8 + gi) * 68 + ks * 8 + 2 * ti]);
                uint32_t b0 = __float_as_uint(kb.x), b1 = __float_as_uint(kb.y);
                mma_tf32_16n8k8(s0[j], a00, a01, a02, a03, b0, b1);
                mma_tf32_16n8k8(s1[j], a10, a11, a12, a13, b0, b1);
            }
        }

        {
            float mloc0 = -INFINITY, mloc1 = -INFINITY;
            #pragma unroll
            for (int j = 0; j < 8; j++) {
                float b0 = sBias[j * 8 + 2 * ti];
                float b1 = sBias[j * 8 + 2 * ti + 1];
                s0[j][0] = fminf(fmaxf(s0[j][0], -10000.0f), 10000.0f) + b0;
                s0[j][1] = fminf(fmaxf(s0[j][1], -10000.0f), 10000.0f) + b1;
                s0[j][2] = fminf(fmaxf(s0[j][2], -10000.0f), 10000.0f) + b0;
                s0[j][3] = fminf(fmaxf(s0[j][3], -10000.0f), 10000.0f) + b1;
                mloc0 = fmaxf(mloc0, fmaxf(s0[j][0], s0[j][1]));
                mloc1 = fmaxf(mloc1, fmaxf(s0[j][2], s0[j][3]));
            }
            mloc0 = fmaxf(mloc0, __shfl_xor_sync(0xffffffffu, mloc0, 1));
            mloc0 = fmaxf(mloc0, __shfl_xor_sync(0xffffffffu, mloc0, 2));
            mloc1 = fmaxf(mloc1, __shfl_xor_sync(0xffffffffu, mloc1, 1));
            mloc1 = fmaxf(mloc1, __shfl_xor_sync(0xffffffffu, mloc1, 2));
            float mn0 = fmaxf(m00, mloc0);
            float mn1 = fmaxf(m01, mloc1);
            float corr0 = __expf(m00 - mn0);
            float corr1 = __expf(m01 - mn1);
            m00 = mn0; m01 = mn1;
            float sum0 = 0.0f, sum1 = 0.0f;
            #pragma unroll
            for (int j = 0; j < 8; j++) {
                s0[j][0] = __expf(s0[j][0] - mn0);
                s0[j][1] = __expf(s0[j][1] - mn0);
                s0[j][2] = __expf(s0[j][2] - mn1);
                s0[j][3] = __expf(s0[j][3] - mn1);
                sum0 += s0[j][0] + s0[j][1];
                sum1 += s0[j][2] + s0[j][3];
            }
            sum0 += __shfl_xor_sync(0xffffffffu, sum0, 1);
            sum0 += __shfl_xor_sync(0xffffffffu, sum0, 2);
            sum1 += __shfl_xor_sync(0xffffffffu, sum1, 1);
            sum1 += __shfl_xor_sync(0xffffffffu, sum1, 2);
            l00 = l00 * corr0 + sum0;
            l01 = l01 * corr1 + sum1;
            #pragma unroll
            for (int j = 0; j < 8; j++) {
                o0[j][0] *= corr0; o0[j][1] *= corr0;
                o0[j][2] *= corr1; o0[j][3] *= corr1;
            }
        }
        {
            float mloc0 = -INFINITY, mloc1 = -INFINITY;
            #pragma unroll
            for (int j = 0; j < 8; j++) {
                float b0 = sBias[j * 8 + 2 * ti];
                float b1 = sBias[j * 8 + 2 * ti + 1];
                s1[j][0] = fminf(fmaxf(s1[j][0], -10000.0f), 10000.0f) + b0;
                s1[j][1] = fminf(fmaxf(s1[j][1], -10000.0f), 10000.0f) + b1;
                s1[j][2] = fminf(fmaxf(s1[j][2], -10000.0f), 10000.0f) + b0;
                s1[j][3] = fminf(fmaxf(s1[j][3], -10000.0f), 10000.0f) + b1;
                mloc0 = fmaxf(mloc0, fmaxf(s1[j][0], s1[j][1]));
                mloc1 = fmaxf(mloc1, fmaxf(s1[j][2], s1[j][3]));
            }
            mloc0 = fmaxf(mloc0, __shfl_xor_sync(0xffffffffu, mloc0, 1));
            mloc0 = fmaxf(mloc0, __shfl_xor_sync(0xffffffffu, mloc0, 2));
            mloc1 = fmaxf(mloc1, __shfl_xor_sync(0xffffffffu, mloc1, 1));
            mloc1 = fmaxf(mloc1, __shfl_xor_sync(0xffffffffu, mloc1, 2));
            float mn0 = fmaxf(m10, mloc0);
            float mn1 = fmaxf(m11, mloc1);
            float corr0 = __expf(m10 - mn0);
            float corr1 = __expf(m11 - mn1);
            m10 = mn0; m11 = mn1;
            float sum0 = 0.0f, sum1 = 0.0f;
            #pragma unroll
            for (int j = 0; j < 8; j++) {
                s1[j][0] = __expf(s1[j][0] - mn0);
                s1[j][1] = __expf(s1[j][1] - mn0);
                s1[j][2] = __expf(s1[j][2] - mn1);
                s1[j][3] = __expf(s1[j][3] - mn1);
                sum0 += s1[j][0] + s1[j][1];
                sum1 += s1[j][2] + s1[j][3];
            }
            sum0 += __shfl_xor_sync(0xffffffffu, sum0, 1);
            sum0 += __shfl_xor_sync(0xffffffffu, sum0, 2);
            sum1 += __shfl_xor_sync(0xffffffffu, sum1, 1);
            sum1 += __shfl_xor_sync(0xffffffffu, sum1, 2);
            l10 = l10 * corr0 + sum0;
            l11 = l11 * corr1 + sum1;
            #pragma unroll
            for (int j = 0; j < 8; j++) {
                o1[j][0] *= corr0; o1[j][1] *= corr0;
                o1[j][2] *= corr1; o1[j][3] *= corr1;
            }
        }

        {
            const int qb   = lane & ~3;
            const int src0 = qb + (ti >> 1);
            const int src1 = src0 + 2;
            const bool odd = (ti & 1);
            #pragma unroll
            for (int kb = 0; kb < 8; kb++) {
                float v00 = __shfl_sync(0xffffffffu, s0[kb][0], src0);
                float v01 = __shfl_sync(0xffffffffu, s0[kb][1], src0);
                float v20 = __shfl_sync(0xffffffffu, s0[kb][0], src1);
                float v21 = __shfl_sync(0xffffffffu, s0[kb][1], src1);
                float v10 = __shfl_sync(0xffffffffu, s0[kb][2], src0);
                float v11 = __shfl_sync(0xffffffffu, s0[kb][3], src0);
                float v30 = __shfl_sync(0xffffffffu, s0[kb][2], src1);
                float v31 = __shfl_sync(0xffffffffu, s0[kb][3], src1);
                uint32_t a0 = f2tf32(odd ? v01 : v00);
                uint32_t a1 = f2tf32(odd ? v11 : v10);
                uint32_t a2 = f2tf32(odd ? v21 : v20);
                uint32_t a3 = f2tf32(odd ? v31 : v30);
                float w00 = __shfl_sync(0xffffffffu, s1[kb][0], src0);
                float w01 = __shfl_sync(0xffffffffu, s1[kb][1], src0);
                float w20 = __shfl_sync(0xffffffffu, s1[kb][0], src1);
                float w21 = __shfl_sync(0xffffffffu, s1[kb][1], src1);
                float w10 = __shfl_sync(0xffffffffu, s1[kb][2], src0);
                float w11 = __shfl_sync(0xffffffffu, s1[kb][3], src0);
                float w30 = __shfl_sync(0xffffffffu, s1[kb][2], src1);
                float w31 = __shfl_sync(0xffffffffu, s1[kb][3], src1);
                uint32_t c0 = f2tf32(odd ? w01 : w00);
                uint32_t c1 = f2tf32(odd ? w11 : w10);
                uint32_t c2 = f2tf32(odd ? w21 : w20);
                uint32_t c3 = f2tf32(odd ? w31 : w30);
                #pragma unroll
                for (int j = 0; j < 8; j++) {
                    uint32_t b0 = __float_as_uint(sV[(kb * 8 + ti) * 72 + j * 8 + gi]);
                    uint32_t b1 = __float_as_uint(sV[(kb * 8 + ti + 4) * 72 + j * 8 + gi]);
                    mma_tf32_16n8k8(o0[j], a0, a1, a2, a3, b0, b1);
                    mma_tf32_16n8k8(o1[j], c0, c1, c2, c3, b0, b1);
                }
            }
        }
        __syncthreads();
    }

    // ---- normalize, round to tf32, write context [B, S, H] ----
    float i00 = 1.0f / l00, i01 = 1.0f / l01;
    float i10 = 1.0f / l10, i11 = 1.0f / l11;
    int row0 = q0 + wid * 32 + gi;
    #pragma unroll
    for (int j = 0; j < 8; j++) {
        int c = h * HD + j * 8 + 2 * ti;
        *reinterpret_cast<float2*>(&CTX[(size_t)(b * SS + row0) * HH + c]) =
            make_float2(cvtf(o0[j][0] * i00), cvtf(o0[j][1] * i00));
        *reinterpret_cast<float2*>(&CTX[(size_t)(b * SS + row0 + 8) * HH + c]) =
            make_float2(cvtf(o0[j][2] * i01), cvtf(o0[j][3] * i01));
        *reinterpret_cast<float2*>(&CTX[(size_t)(b * SS + row0 + 16) * HH + c]) =
            make_float2(cvtf(o1[j][0] * i10), cvtf(o1[j][1] * i10));
        *reinterpret_cast<float2*>(&CTX[(size_t)(b * SS + row0 + 24) * HH + c]) =
            make_float2(cvtf(o1[j][2] * i11), cvtf(o1[j][3] * i11));
    }
}

// =================================================================
extern "C" void kernel_launch(void* const* d_in, const int* in_sizes, int n_in,
                              void* d_out, int out_size)
{
    const float* X    = (const float*)d_in[0];
    const int*   mask = (const int*)d_in[1];
    const float* WQ   = (const float*)d_in[2];
    const float* WK   = (const float*)d_in[3];
    const float* WV   = (const float*)d_in[4];
    const float* WO   = (const float*)d_in[5];
    float* out = (float*)d_out;

    float *qb, *kb, *vb, *cb, *xc, *w0, *w1, *w2, *w3;
    cudaGetSymbolAddress((void**)&qb, g_Q);
    cudaGetSymbolAddress((void**)&kb, g_K);
    cudaGetSymbolAddress((void**)&vb, g_V);
    cudaGetSymbolAddress((void**)&cb, g_CTX);
    cudaGetSymbolAddress((void**)&xc, g_Xc);
    cudaGetSymbolAddress((void**)&w0, g_Wc0);
    cudaGetSymbolAddress((void**)&w1, g_Wc1);
    cudaGetSymbolAddress((void**)&w2, g_Wc2);
    cudaGetSymbolAddress((void**)&w3, g_Wc3);

    const int nx4 = MROWS * HH / 4;   // 1M
    const int nw4 = GK * HH / 4;      // 256K
    cvt_tf32_kernel<<<(nx4 + 255) / 256, 256>>>(X, xc, nx4);
    cvt4_tf32_kernel<<<dim3((nw4 + 255) / 256, 4), 256>>>(
        WQ, WK, WV, WO, w0, w1, w2, w3, nw4);

    size_t gsmem = (size_t)STAGES * (SA_TILE + SB_TILE) * sizeof(float);
    cudaFuncSetAttribute(gemm_tf32_cp, cudaFuncAttributeMaxDynamicSharedMemorySize, (int)gsmem);

    // fused Q/K/V projections: one launch, gridDim.z selects weight/output
    gemm_tf32_cp<<<dim3(HH / 128, MROWS / 128, 3), 128, gsmem>>>(
        xc, w0, w1, w2, qb, kb, vb, 1);

    size_t smem = (size_t)(128 * 68 + 64 * 68 + 64 * 72 + 64) * sizeof(float);
    cudaFuncSetAttribute(attn_kernel, cudaFuncAttributeMaxDynamicSharedMemorySize, (int)smem);
    attn_kernel<<<dim3(SS / QTILE, NHH, BB), 128, smem>>>(qb, kb, vb, mask, cb);

    // O projection
    gemm_tf32_cp<<<dim3(HH / 128, MROWS / 128, 1), 128, gsmem>>>(
        cb, w3, w3, w3, out, out, out, 0);
}